// round 10
// baseline (speedup 1.0000x reference)
#include <cuda_runtime.h>
#include <math.h>

// Problem constants
#define BATCH 16
#define LROWS 192   // 6*L rows of raw
#define AC    2046  // attributor columns
#define MC    2048  // M = A + 2
#define LD    32    // L (W_2 output dim)
#define TC    32    // column slots per block
#define NCB   64    // c-blocks (64*32 = 2048 slots: 2046 cols + 2 specials)
#define BPB   4     // batches per block
#define NBG   (BATCH / BPB)   // 4 batch-groups

// Scratch (device globals; no allocation allowed)
__device__ float g_wq[BATCH][2][64];
__device__ float g_wk[BATCH][2][64];
__device__ float g_A[2][MC];           // adj[m][col_n]
__device__ float g_P[2][MC];           // adj[m][col_n] * iw[m][col_n]
__device__ float g_R[2][MC];           // adj[col_n][m] * iw[col_n][m]

// ---------------------------------------------------------------------------
// Kernel 1 (prep): wq/wk folds + adj/iw packing + d_out zeroing.
// ---------------------------------------------------------------------------
__global__ __launch_bounds__(128) void prep_kernel(
    const float* __restrict__ user, const float* __restrict__ item,
    const float* __restrict__ W2,
    const float* __restrict__ adj, const float* __restrict__ iw,
    float* __restrict__ out) {

    int blk = blockIdx.x;
    int t = threadIdx.x;

    if (blk < 32) {
        int b = blk >> 1;
        int n = blk & 1;
        const float* src = (n ? item : user) + b * LROWS;
        __shared__ float W2s[128 * 33];
        __shared__ float xr[128];
        __shared__ float qs[32];
        __shared__ float ks[32];

        xr[t] = fmaxf(src[t], 0.0f);
        #pragma unroll
        for (int i = 0; i < 32; i++) {
            int idx = t + i * 128;
            W2s[(idx >> 5) * 33 + (idx & 31)] = W2[idx];
        }
        __syncthreads();

        if (t < 32) {
            float s = 0.0f;
            #pragma unroll
            for (int j = 0; j < 64; j++) s = fmaf(xr[j], W2s[j * 33 + t], s);
            qs[t] = s;
        } else if (t < 64) {
            int l = t - 32;
            float s = 0.0f;
            #pragma unroll
            for (int j = 0; j < 64; j++) s = fmaf(xr[64 + j], W2s[(64 + j) * 33 + l], s);
            ks[l] = s;
        }
        __syncthreads();
        if (t < 64) {
            float swq = 0.0f, swk = 0.0f;
            #pragma unroll
            for (int l = 0; l < 32; l++) {
                swq = fmaf(W2s[t * 33 + l],        ks[l], swq);
                swk = fmaf(W2s[(64 + t) * 33 + l], qs[l], swk);
            }
            g_wq[b][n][t] = swq;
            g_wk[b][n][t] = swk;
        }
    } else {
        if (blk == 32) {
            float4 z = make_float4(0.f, 0.f, 0.f, 0.f);
            ((float4*)out)[t]       = z;
            ((float4*)out)[t + 128] = z;
        }
        int m = (blk - 32) * 128 + t;
        size_t row = (size_t)m * MC;
        float a0 = adj[row];
        float a1 = adj[row + (MC - 1)];
        g_A[0][m] = a0;
        g_A[1][m] = a1;
        g_P[0][m] = a0 * iw[row];
        g_P[1][m] = a1 * iw[row + (MC - 1)];
        g_R[0][m] = adj[m] * iw[m];
        size_t lastrow = (size_t)(MC - 1) * MC + m;
        g_R[1][m] = adj[lastrow] * iw[lastrow];
    }
}

// ---------------------------------------------------------------------------
// Kernel 2 (main): grid (cb=64, bg=4) = 256 blocks, 384 threads.
// Each block owns a 32-column tile, keeps its W1 tile in SMEM, and loops
// over 4 batches with av/wq prefetch pipelining. Global streaming loads are
// attributor-only (8 x float2 per thread per batch, front-batched).
// Special nodes: lane 15 of last cb -> (user, item); their W1 smem entries
// are 1.0 so the compute path is uniform.
// ---------------------------------------------------------------------------
__global__ __launch_bounds__(384) void main_kernel(
    const float* __restrict__ user, const float* __restrict__ item,
    const float* __restrict__ attributor, const float* __restrict__ W1,
    const float* __restrict__ W2, float* __restrict__ out) {

    __shared__ float w_sh[192][34];    // W1 tile, padded stride (8B-aligned, no conflicts)
    __shared__ float Vsh[64][TC + 1];
    __shared__ float hq_p[8][2][TC];   // [jq][n][slot]
    __shared__ float hk_p[8][2][TC];
    __shared__ float c_sh[2][TC];
    __shared__ float wq_sh[2][2][64];  // [buf][n][j]
    __shared__ float wk_sh[2][2][64];
    __shared__ float W2e[64][LD];      // W2 rows 128..191
    __shared__ float Ssh_p[2][2][64];  // [mm-half][n][j]
    __shared__ float aA[2][TC], aP[2][TC], aR[2][TC];

    int bg = blockIdx.y;
    int cb = blockIdx.x;
    int t  = threadIdx.x;
    int group = t >> 7;          // 0:Q 1:K 2:V
    int sub   = t & 127;
    int jq    = sub >> 4;        // 8 rows each
    int lane  = sub & 15;        // 2 cols each
    int c0    = cb * TC;
    int c     = c0 + 2 * lane;
    int row0  = group * 64 + jq * 8;
    int jj0   = jq * 8;
    bool lastcb  = (cb == NCB - 1);
    bool special = lastcb && (lane == 15);
    int b_first = bg * BPB;

    // ---- prologue: W1 tile, W2e, adj/iw slices, wq/wk buf0 — all issued up front
    #pragma unroll
    for (int i = 0; i < 16; i++) {
        int idx = t + i * 384;           // 0..6143
        int r = idx >> 5, cc = idx & 31;
        int gc = c0 + cc;
        w_sh[r][cc] = (gc < AC) ? W1[(size_t)r * AC + gc] : 1.0f;
    }
    if (t < 256) {
        ((float4*)W2e)[t]       = ((const float4*)(W2 + 128 * LD))[t];
        ((float4*)W2e)[t + 256] = ((const float4*)(W2 + 128 * LD))[t + 256];
    }
    if (t < 64) {
        int n = t >> 5, mm = t & (TC - 1);
        int m = c0 + mm + 1;
        if (lastcb && mm == 30) m = 0;
        else if (lastcb && mm == 31) m = MC - 1;
        aA[n][mm] = g_A[n][m];
        aP[n][mm] = g_P[n][m];
        aR[n][mm] = g_R[n][m];
    } else if (t >= 128 && t < 256) {
        int tt = t - 128;
        ((float*)wq_sh[0])[tt] = ((const float*)g_wq[b_first])[tt];
        ((float*)wk_sh[0])[tt] = ((const float*)g_wk[b_first])[tt];
    }

    auto LOADAV = [&](float2 (&dst)[8], int b) {
        if (special) {
            const float* uu = user + b * LROWS + row0;
            const float* ii = item + b * LROWS + row0;
            #pragma unroll
            for (int r = 0; r < 8; r++) { dst[r].x = uu[r]; dst[r].y = ii[r]; }
        } else {
            const float* ap = attributor + ((size_t)b * LROWS + row0) * AC + c;
            #pragma unroll
            for (int r = 0; r < 8; r++)
                dst[r] = *(const float2*)(ap + (size_t)r * AC);
        }
    };

    float2 av[2][8];
    LOADAV(av[0], b_first);
    __syncthreads();

    #pragma unroll
    for (int b4 = 0; b4 < BPB; b4++) {
        int b = b_first + b4;
        const int cur = b4 & 1, nxt = cur ^ 1;

        // prefetch next batch's attributor tile (issues before compute consumes av[cur])
        if (b4 < BPB - 1) LOADAV(av[nxt], b + 1);

        // phase 1: compute h partials / V tile
        if (group < 2) {
            const float (*wsel)[64] = (group == 0) ? wq_sh[cur] : wk_sh[cur];
            float hA0 = 0.f, hA1 = 0.f, hB0 = 0.f, hB1 = 0.f;
            #pragma unroll
            for (int r = 0; r < 8; r++) {
                float w0 = w_sh[row0 + r][2 * lane];
                float w1 = w_sh[row0 + r][2 * lane + 1];
                float x0 = fmaxf(av[cur][r].x * w0, 0.0f);
                float x1 = fmaxf(av[cur][r].y * w1, 0.0f);
                hA0 = fmaf(x0, wsel[0][jj0 + r], hA0);
                hA1 = fmaf(x0, wsel[1][jj0 + r], hA1);
                hB0 = fmaf(x1, wsel[0][jj0 + r], hB0);
                hB1 = fmaf(x1, wsel[1][jj0 + r], hB1);
            }
            if (group == 0) {
                hq_p[jq][0][2 * lane] = hA0;      hq_p[jq][1][2 * lane] = hA1;
                hq_p[jq][0][2 * lane + 1] = hB0;  hq_p[jq][1][2 * lane + 1] = hB1;
            } else {
                hk_p[jq][0][2 * lane] = hA0;      hk_p[jq][1][2 * lane] = hA1;
                hk_p[jq][0][2 * lane + 1] = hB0;  hk_p[jq][1][2 * lane + 1] = hB1;
            }
        } else {
            #pragma unroll
            for (int r = 0; r < 8; r++) {
                float w0 = w_sh[row0 + r][2 * lane];
                float w1 = w_sh[row0 + r][2 * lane + 1];
                Vsh[jj0 + r][2 * lane]     = fmaxf(av[cur][r].x * w0, 0.0f);
                Vsh[jj0 + r][2 * lane + 1] = fmaxf(av[cur][r].y * w1, 0.0f);
            }
        }
        __syncthreads();

        // phase 2: causal (t<64); wq/wk prefetch for next batch (t in [128,256))
        if (t < 64) {
            int n = t >> 5, mm = t & (TC - 1);
            float hq = 0.f, hk = 0.f;
            #pragma unroll
            for (int q = 0; q < 8; q++) { hq += hq_p[q][n][mm]; hk += hk_p[q][n][mm]; }
            float d = hq * aP[n][mm] - hk * aR[n][mm];
            c_sh[n][mm] = aA[n][mm] / (1.0f + expf(-d));
        } else if (t >= 128 && t < 256 && b4 < BPB - 1) {
            int tt = t - 128;
            ((float*)wq_sh[nxt])[tt] = ((const float*)g_wq[b + 1])[tt];
            ((float*)wk_sh[nxt])[tt] = ((const float*)g_wk[b + 1])[tt];
        }
        __syncthreads();

        // phase 3: partial S over mm halves (256 threads, 16 slots each)
        if (t < 256) {
            int mh = t >> 7;
            int n  = (t >> 6) & 1;
            int j  = t & 63;
            int m0 = mh * 16;
            float s = 0.0f;
            #pragma unroll
            for (int mm = 0; mm < 16; mm++)
                s = fmaf(Vsh[j][m0 + mm], c_sh[n][m0 + mm], s);
            Ssh_p[mh][n][j] = s;
        }
        __syncthreads();

        // phase 4: projection + atomic accumulate
        if (t < 64) {
            int l = t >> 1;
            int n = t & 1;
            float s = 0.0f;
            #pragma unroll
            for (int j = 0; j < 64; j++)
                s = fmaf(W2e[j][l], Ssh_p[0][n][j] + Ssh_p[1][n][j], s);
            atomicAdd(&out[b * 64 + l * 2 + n], s);
        }
        __syncthreads();
    }
}

extern "C" void kernel_launch(void* const* d_in, const int* in_sizes, int n_in,
                              void* d_out, int out_size) {
    const float* user       = (const float*)d_in[0];
    const float* item       = (const float*)d_in[1];
    const float* attributor = (const float*)d_in[2];
    const float* adj        = (const float*)d_in[3];
    const float* iw         = (const float*)d_in[4];
    const float* W1         = (const float*)d_in[5];
    const float* W2         = (const float*)d_in[6];
    float* out = (float*)d_out;

    prep_kernel<<<48, 128>>>(user, item, W2, adj, iw, out);
    main_kernel<<<dim3(NCB, NBG), 384>>>(user, item, attributor, W1, W2, out);
}